// round 17
// baseline (speedup 1.0000x reference)
#include <cuda_runtime.h>
#include <cuda_fp16.h>
#include <math.h>
#include <stdint.h>

#define BB 2
#define TT 2048
#define DIMM 1024
#define HH 16
#define MM (BB*TT)
#define TKE 1024
#define NCH 16
#define EPSF 1.1920928955078125e-07f
#define GSMEM (3*32768)
#define SMQ (64*68*4 + 64*132*4)   /* Ps 17408 + Ws 33792 = 51200 B */

__device__ __align__(256) __half g_xs[(size_t)MM * TKE];
__device__ __align__(256) __half g_wkv[(size_t)2048 * TKE];  /* head-interleaved [k_h|v_h] */
__device__ __align__(256) __half g_gf[(size_t)TT * 1024];    /* Gflat fp16 [t][h*64+jj] */
__device__ __align__(256) __half g_q[(size_t)BB * 1024 * 1024]; /* Q fp16 [b][o][h*64+jj] */
__device__ __align__(256) float g_kv[(size_t)MM * DIMM];
__device__ __align__(256) float g_F[TT * 64];
__device__ __align__(256) float g_P[BB * HH * 64 * 64];

__device__ __forceinline__ uint32_t smem_u32(const void* p) {
    uint32_t a;
    asm("{ .reg .u64 t; cvta.to.shared.u64 t, %1; cvt.u32.u64 %0, t; }" : "=r"(a) : "l"(p));
    return a;
}
__device__ __forceinline__ void cpa16(uint32_t d, const void* s) {
    asm volatile("cp.async.cg.shared.global [%0], [%1], 16;" :: "r"(d), "l"(s));
}
/* fp32 Cody-Waite 2pi reduction: P1 products exact (n has <=8 mantissa bits) */
__device__ __forceinline__ void sincos_cw(float ang, float* s, float* c) {
    const float INV2PI = 0.15915494309189535f;
    const float P1 = 6.28125f;
    const float P2 = 1.9353071795864769e-3f;
    float n = rintf(ang * INV2PI);
    float r = fmaf(-n, P1, ang);
    r = fmaf(-n, P2, r);
    sincosf(r, s, c);
}
__device__ __forceinline__ void store_h4(__half* dst, float4 v) {
    __half2* d = (__half2*)dst;
    d[0] = __floats2half2_rn(v.x, v.y);
    d[1] = __floats2half2_rn(v.z, v.w);
}
__device__ __forceinline__ uint4 ldsm4(uint32_t a) {
    uint4 r;
    asm volatile("ldmatrix.sync.aligned.m8n8.x4.shared.b16 {%0,%1,%2,%3}, [%4];"
                 : "=r"(r.x), "=r"(r.y), "=r"(r.z), "=r"(r.w) : "r"(a));
    return r;
}
__device__ __forceinline__ void mma16816(float* c, uint4 a, uint32_t b0, uint32_t b1) {
    asm volatile("mma.sync.aligned.m16n8k16.row.col.f32.f16.f16.f32 "
                 "{%0,%1,%2,%3}, {%4,%5,%6,%7}, {%8,%9}, {%0,%1,%2,%3};"
                 : "+f"(c[0]), "+f"(c[1]), "+f"(c[2]), "+f"(c[3])
                 : "r"(a.x), "r"(a.y), "r"(a.z), "r"(a.w), "r"(b0), "r"(b1));
}

/* ---- fused prep: convw (0..2047) | trig (2048..4095) | rmsnorm (4096..8191) | zeroP (8192..8223) ---- */
__global__ void __launch_bounds__(256) k_prep(const float* __restrict__ states,
                                              const float* __restrict__ lnw,
                                              const float* __restrict__ Wk,
                                              const float* __restrict__ Wv,
                                              const float* __restrict__ angles,
                                              const float* __restrict__ hdelta) {
    const int bid = blockIdx.x, tid = threadIdx.x;
    if (bid < 2048) {                                   /* KV weight conversion -> fp16 */
        int row = bid;
        int h = row >> 7, c = row & 127;
        const float* src = (c < 64) ? Wk + (size_t)(h * 64 + c) * 1024
                                    : Wv + (size_t)(h * 64 + c - 64) * 1024;
        __half* dst = g_wkv + (size_t)row * TKE;
        float4 v = ((const float4*)src)[tid];
        store_h4(dst + tid * 4, v);
    } else if (bid < 4096) {                            /* trig tables: F fp32, Gflat fp16 */
        int t = bid - 2048;
        __shared__ float w[32], hd[16];
        if (tid < 32) w[tid] = angles[tid];
        if (tid >= 32 && tid < 48) hd[tid - 32] = hdelta[tid - 32];
        __syncthreads();
        if (tid < 32) {
            float s, c; sincos_cw((float)t * w[tid], &s, &c);
            g_F[t * 64 + tid] = c; g_F[t * 64 + 32 + tid] = s;
        }
        for (int e = tid; e < 512; e += 256) {
            int h = e >> 5, j = e & 31;
            float s, c; sincos_cw(((float)t + hd[h]) * w[j], &s, &c);
            g_gf[(size_t)t * 1024 + h * 64 + j]      = __float2half(c * 0.03125f);
            g_gf[(size_t)t * 1024 + h * 64 + 32 + j] = __float2half(s * 0.03125f);
        }
    } else if (bid < 8192) {                            /* RMSNorm -> fp16 A */
        int row = bid - 4096;
        float4 v = ((const float4*)(states + (size_t)row * DIMM))[tid];
        float ss = v.x*v.x + v.y*v.y + v.z*v.z + v.w*v.w;
        #pragma unroll
        for (int o = 16; o > 0; o >>= 1) ss += __shfl_xor_sync(0xffffffffu, ss, o);
        __shared__ float wsum[8];
        if ((tid & 31) == 0) wsum[tid >> 5] = ss;
        __syncthreads();
        if (tid < 8) {
            float s2 = wsum[tid];
            #pragma unroll
            for (int o = 4; o > 0; o >>= 1) s2 += __shfl_xor_sync(0xffu, s2, o);
            if (tid == 0) wsum[0] = s2;
        }
        __syncthreads();
        float sc = rsqrtf(wsum[0] * (1.0f / DIMM) + EPSF);
        float4 w = ((const float4*)lnw)[tid];
        float4 o = make_float4(v.x*sc*w.x, v.y*sc*w.y, v.z*sc*w.z, v.w*sc*w.w);
        store_h4(g_xs + (size_t)row * TKE + tid * 4, o);
    } else {                                            /* zero g_P: 32 blocks x 4096 floats */
        int base = (bid - 8192) * 4096 + tid * 4;
        float4 z = make_float4(0.f, 0.f, 0.f, 0.f);
        #pragma unroll
        for (int i = 0; i < 4; i++)
            *(float4*)(g_P + base + i * 1024) = z;
    }
}

/* ---- warp-MMA GEMM (fp16), single-sync pipeline; mode0 fuses softmax*v ----
   mode 1: A = Gflat table (row t = global row mod 2048), B = Q[b]           */
__global__ void __launch_bounds__(256, 2) k_mma(int mode, float* __restrict__ outp,
                                                const float* __restrict__ bo,
                                                const float* __restrict__ bk,
                                                const float* __restrict__ bv,
                                                const int* __restrict__ mask) {
    extern __shared__ __align__(16) char smc[];
    __shared__ float bks[64], bvs[64];
    const int tid = threadIdx.x;
    const int rowBase = blockIdx.x * 128, colBase = blockIdx.y * 128;
    uint32_t sb = smem_u32(smc);

    if (mode == 0) {
        if (tid < 64)            bks[tid]      = bk[blockIdx.y * 64 + tid];
        else if (tid < 128)      bvs[tid - 64] = bv[blockIdx.y * 64 + tid - 64];
    }

    const int lr = tid >> 1, lsg = (tid & 1) * 4;
    const __half* gA;
    const __half* gB;
    if (mode) {
        int bq = rowBase >> 11;
        gA = g_gf + (size_t)((rowBase & 2047) + lr) * TKE + lsg * 8;
        gB = g_q + (size_t)bq * 1048576 + (size_t)(colBase + lr) * TKE + lsg * 8;
    } else {
        gA = g_xs  + (size_t)(rowBase + lr) * TKE + lsg * 8;
        gB = g_wkv + (size_t)(colBase + lr) * TKE + lsg * 8;
    }
    uint32_t sw[4];
    #pragma unroll
    for (int s = 0; s < 4; s++) {
        uint32_t o = lr * 128 + (lsg + s) * 16;
        sw[s] = o ^ ((o >> 3) & 0x70);
    }
    #define LOADC(c) do {                                                         \
        uint32_t stA = sb + ((c) % 3) * 32768, stB = stA + 16384;                 \
        const __half* pa = gA + (size_t)(c) * 64;                                 \
        const __half* pb = gB + (size_t)(c) * 64;                                 \
        cpa16(stA + sw[0], pa);      cpa16(stB + sw[0], pb);                      \
        cpa16(stA + sw[1], pa + 8);  cpa16(stB + sw[1], pb + 8);                  \
        cpa16(stA + sw[2], pa + 16); cpa16(stB + sw[2], pb + 16);                 \
        cpa16(stA + sw[3], pa + 24); cpa16(stB + sw[3], pb + 24);                 \
        asm volatile("cp.async.commit_group;" ::: "memory"); } while (0)

    const int w = tid >> 5, lane = tid & 31;
    const int wm = w & 1, wn = w >> 1;
    const int arow = wm * 64 + ((lane >> 3) & 1) * 8 + (lane & 7);
    const uint32_t akh = (lane >> 4) * 16;
    const uint32_t aSwz = (arow & 7) * 16;
    uint32_t aOff[4];
    #pragma unroll
    for (int mt = 0; mt < 4; mt++) aOff[mt] = (arow + mt * 16) * 128;
    const int bn = wn * 32 + ((lane >> 4) & 1) * 8 + (lane & 7);
    const uint32_t bkh = ((lane >> 3) & 1) * 16;
    const uint32_t bSwz = (bn & 7) * 16;
    uint32_t bOff[2];
    bOff[0] = bn * 128; bOff[1] = (bn + 16) * 128;

    float acc[4][4][4];
    #pragma unroll
    for (int i = 0; i < 4; i++)
        #pragma unroll
        for (int j = 0; j < 4; j++)
            #pragma unroll
            for (int q = 0; q < 4; q++) acc[i][j][q] = 0.0f;

    uint4 Af[2][4]; uint4 Bf[2][2];
    #define LDFRAG(buf, stA, stB, ksv) do {                                       \
        uint32_t ka = ((ksv) * 32 + akh) ^ aSwz;                                  \
        uint32_t kb = ((ksv) * 32 + bkh) ^ bSwz;                                  \
        Af[buf][0] = ldsm4((stA) + aOff[0] + ka);                                 \
        Af[buf][1] = ldsm4((stA) + aOff[1] + ka);                                 \
        Af[buf][2] = ldsm4((stA) + aOff[2] + ka);                                 \
        Af[buf][3] = ldsm4((stA) + aOff[3] + ka);                                 \
        Bf[buf][0] = ldsm4((stB) + bOff[0] + kb);                                 \
        Bf[buf][1] = ldsm4((stB) + bOff[1] + kb); } while (0)

    /* single-sync pipeline: prefetch distance 2, one barrier per chunk */
    LOADC(0); LOADC(1);
    for (int j = 0; j < NCH; j++) {
        if (j < NCH - 1) asm volatile("cp.async.wait_group 1;" ::: "memory");
        else             asm volatile("cp.async.wait_group 0;" ::: "memory");
        __syncthreads();
        uint32_t stA = sb + (j % 3) * 32768, stB = stA + 16384;
        if (j + 2 < NCH) LOADC(j + 2);   /* writes stage (j-1)%3: consumed last iter */
        LDFRAG(0, stA, stB, 0);
        #pragma unroll
        for (int ks = 0; ks < 4; ks++) {
            if (ks < 3) LDFRAG((ks + 1) & 1, stA, stB, ks + 1);
            const int cb = ks & 1;
            uint32_t bb[4][2] = {{Bf[cb][0].x, Bf[cb][0].y}, {Bf[cb][0].z, Bf[cb][0].w},
                                 {Bf[cb][1].x, Bf[cb][1].y}, {Bf[cb][1].z, Bf[cb][1].w}};
            #pragma unroll
            for (int mt = 0; mt < 4; mt++)
                #pragma unroll
                for (int nt = 0; nt < 4; nt++)
                    mma16816(acc[mt][nt], Af[cb][mt], bb[nt][0], bb[nt][1]);
        }
    }
    #undef LOADC
    #undef LDFRAG

    if (mode == 1) {
        const int crow0 = rowBase + wm * 64 + (lane >> 2);
        const int ccol0 = colBase + wn * 32 + (lane & 3) * 2;
        #pragma unroll
        for (int mt = 0; mt < 4; mt++) {
            #pragma unroll
            for (int nt = 0; nt < 4; nt++) {
                int row = crow0 + mt * 16, col = ccol0 + nt * 8;
                float b0 = bo[col], b1 = bo[col + 1];
                float2 v0 = make_float2(acc[mt][nt][0] + b0, acc[mt][nt][1] + b1);
                float2 v1 = make_float2(acc[mt][nt][2] + b0, acc[mt][nt][3] + b1);
                *(float2*)(outp + (size_t)row * 1024 + col) = v0;
                *(float2*)(outp + (size_t)(row + 8) * 1024 + col) = v1;
            }
        }
        return;
    }

    /* mode 0: stage scores to smem, per-row softmax(k)*v -> g_kv */
    __syncthreads();   /* all warps done with smem stages before reuse as Cs */
    float* Cs = (float*)smc;                  /* stride 129: conflict-free */
    const int lrow0 = wm * 64 + (lane >> 2);
    const int lcol0 = wn * 32 + (lane & 3) * 2;
    #pragma unroll
    for (int mt = 0; mt < 4; mt++) {
        #pragma unroll
        for (int nt = 0; nt < 4; nt++) {
            int rr = lrow0 + mt * 16, cc = lcol0 + nt * 8;
            Cs[rr * 129 + cc]           = acc[mt][nt][0];
            Cs[rr * 129 + cc + 1]       = acc[mt][nt][1];
            Cs[(rr + 8) * 129 + cc]     = acc[mt][nt][2];
            Cs[(rr + 8) * 129 + cc + 1] = acc[mt][nt][3];
        }
    }
    __syncthreads();
    {
        const int r = tid >> 1, half = tid & 1;
        float m = (float)mask[rowBase + r];
        float* crow = Cs + r * 129 + half * 32;       /* k: crow[0..31], v: crow[64..95] */
        const float* bkh_ = bks + half * 32;
        const float* bvh_ = bvs + half * 32;
        float mx = -INFINITY;
        #pragma unroll 8
        for (int i = 0; i < 32; i++) {
            float kk = (crow[i] + bkh_[i]) * m;
            crow[i] = kk; mx = fmaxf(mx, kk);
        }
        mx = fmaxf(mx, __shfl_xor_sync(0xffffffffu, mx, 1));
        float sum = 0.0f;
        #pragma unroll 8
        for (int i = 0; i < 32; i++) {
            float e = expf(crow[i] - mx);
            crow[i] = e; sum += e;
        }
        sum += __shfl_xor_sync(0xffffffffu, sum, 1);
        float inv = 1.0f / sum;
        float* dst = g_kv + (size_t)(rowBase + r) * 1024 + blockIdx.y * 64 + half * 32;
        #pragma unroll 8
        for (int i = 0; i < 32; i++)
            dst[i] = crow[i] * inv * (crow[64 + i] + bvh_[i]);
    }
}

/* ---- stage A: P[b,h,jj,d] = sum_l F[l,jj]*kv[b,l,h,d]; 16 splits x 128 l ---- */
__global__ void __launch_bounds__(256) k_stageA() {
    const int bh = blockIdx.x, b = bh >> 4, h = bh & 15;
    const int lbase0 = blockIdx.y * 128;
    const int tid = threadIdx.x, tx = tid & 15, ty = tid >> 4;
    __shared__ __align__(16) float F[16][64];
    __shared__ __align__(16) float KV[16][64];
    float acc[4][4] = {};
    for (int sub = 0; sub < 8; sub++) {
        int lbase = lbase0 + sub * 16;
        *(float4*)&F[ty][tx*4]  = *(const float4*)(g_F + (size_t)(lbase + ty) * 64 + tx * 4);
        *(float4*)&KV[ty][tx*4] = *(const float4*)(g_kv + (size_t)(b * TT + lbase + ty) * DIMM + h * 64 + tx * 4);
        __syncthreads();
        #pragma unroll
        for (int l = 0; l < 16; l++) {
            float4 f4 = *(const float4*)&F[l][ty * 4];
            float4 k4 = *(const float4*)&KV[l][tx * 4];
            float ff[4] = {f4.x, f4.y, f4.z, f4.w};
            float kk[4] = {k4.x, k4.y, k4.z, k4.w};
            #pragma unroll
            for (int i = 0; i < 4; i++)
                #pragma unroll
                for (int j = 0; j < 4; j++) acc[i][j] += ff[i] * kk[j];
        }
        __syncthreads();
    }
    float* Pp = g_P + (size_t)bh * 4096;
    #pragma unroll
    for (int i = 0; i < 4; i++)
        #pragma unroll
        for (int j = 0; j < 4; j++)
            atomicAdd(&Pp[(ty*4 + i) * 64 + tx*4 + j], acc[i][j]);
}

/* ---- k_Q: Q[b][o][h*64+jj] = sum_d P[b,h,jj,d] * Wo[o, h*64+d]  (fp16 out) ---- */
__global__ void __launch_bounds__(256) k_Q(const float* __restrict__ Wo) {
    extern __shared__ __align__(16) float smq[];
    float* Ps = smq;              /* [64][68]: Ps[d][jj] */
    float* Ws = smq + 64 * 68;    /* [64][132]: Ws[d][o] */
    const int bh = blockIdx.x, b = bh >> 4, h = bh & 15;
    const int obase = blockIdx.y * 128;
    const int tid = threadIdx.x, tx = tid & 15, ty = tid >> 4;

    const float* Pp = g_P + (size_t)bh * 4096;
    for (int e = tid; e < 4096; e += 256) {
        int jj = e >> 6, d = e & 63;
        Ps[d * 68 + jj] = Pp[e];
    }
    for (int e = tid; e < 128 * 16; e += 256) {
        int o = e >> 4, d4 = (e & 15) * 4;
        float4 w = *(const float4*)(Wo + (size_t)(obase + o) * DIMM + h * 64 + d4);
        Ws[(d4 + 0) * 132 + o] = w.x; Ws[(d4 + 1) * 132 + o] = w.y;
        Ws[(d4 + 2) * 132 + o] = w.z; Ws[(d4 + 3) * 132 + o] = w.w;
    }
    __syncthreads();

    /* thread: jj block = ty*4..+3, o block = tx*8..+7 */
    float4 accv[4][2] = {};
    for (int d = 0; d < 64; d++) {
        float4 w0 = *(const float4*)&Ws[d * 132 + tx * 8];
        float4 w1 = *(const float4*)&Ws[d * 132 + tx * 8 + 4];
        #pragma unroll
        for (int i = 0; i < 4; i++) {
            float p = Ps[d * 68 + ty * 4 + i];
            accv[i][0].x += p * w0.x; accv[i][0].y += p * w0.y;
            accv[i][0].z += p * w0.z; accv[i][0].w += p * w0.w;
            accv[i][1].x += p * w1.x; accv[i][1].y += p * w1.y;
            accv[i][1].z += p * w1.z; accv[i][1].w += p * w1.w;
        }
    }
    /* store: Q[b][o][h*64 + jj], scalar halves */
    __half* Qb = g_q + (size_t)b * 1048576;
    #pragma unroll
    for (int i = 0; i < 4; i++) {
        int r = h * 64 + ty * 4 + i;
        float vals[8] = {accv[i][0].x, accv[i][0].y, accv[i][0].z, accv[i][0].w,
                         accv[i][1].x, accv[i][1].y, accv[i][1].z, accv[i][1].w};
        #pragma unroll
        for (int oi = 0; oi < 8; oi++)
            Qb[(size_t)(obase + tx * 8 + oi) * 1024 + r] = __float2half(vals[oi]);
    }
}

extern "C" void kernel_launch(void* const* d_in, const int* in_sizes, int n_in,
                              void* d_out, int out_size) {
    const float* states = (const float*)d_in[0];
    const int*   mask   = (const int*)  d_in[1];
    const float* lnw    = (const float*)d_in[2];
    const float* angles = (const float*)d_in[3];
    const float* hdelta = (const float*)d_in[4];
    const float* Wk = (const float*)d_in[7];
    const float* bk = (const float*)d_in[8];
    const float* Wv = (const float*)d_in[9];
    const float* bv = (const float*)d_in[10];
    const float* Wo = (const float*)d_in[11];
    const float* bo = (const float*)d_in[12];
    float* out = (float*)d_out;

    cudaFuncSetAttribute(k_mma, cudaFuncAttributeMaxDynamicSharedMemorySize, GSMEM);
    cudaFuncSetAttribute(k_Q, cudaFuncAttributeMaxDynamicSharedMemorySize, SMQ);

    k_prep<<<8224, 256>>>(states, lnw, Wk, Wv, angles, hdelta);

    dim3 gkv(MM / 128, HH);
    k_mma<<<gkv, 256, GSMEM>>>(0, nullptr, nullptr, bk, bv, mask);

    dim3 ga(BB * HH, 16);
    k_stageA<<<ga, 256>>>();

    dim3 gq(BB * HH, 8);
    k_Q<<<gq, 256, SMQ>>>(Wo);

    dim3 go(MM / 128, DIMM / 128);
    k_mma<<<go, 256, GSMEM>>>(1, out, bo, nullptr, nullptr, nullptr);
}